// round 4
// baseline (speedup 1.0000x reference)
#include <cuda_runtime.h>
#include <math.h>

#define DD 64
#define TWO_PI_F 6.283185307179586f
#define EPS_F 1e-8f

// Device-side scratch (no allocations allowed).
__device__ __align__(16) float g_diag[DD];
__device__ float g_invA[DD * DD];
__device__ float g_coef;
__device__ int g_isdiag;

// ---------------------------------------------------------------------------
// Prep kernel. Diag fast path: parallel diagonal load + smem det product
// (no serial L2 pointer-chase). General path: Gauss-Jordan w/ partial
// pivoting, det from pivots. Single block.
// ---------------------------------------------------------------------------
__global__ void prep_kernel(const float* __restrict__ Sigma,
                            const float* __restrict__ Phi) {
    __shared__ float aug[DD][2 * DD];
    __shared__ float colk[DD];
    __shared__ float sdiag[DD];
    __shared__ int s_offdiag;
    __shared__ float s_det;
    __shared__ int s_piv;
    int tid = threadIdx.x;

    if (tid == 0) s_offdiag = 0;
    // Parallel diagonal fetch (independent loads, full MLP).
    if (tid < DD) sdiag[tid] = Sigma[tid * DD + tid];
    __syncthreads();

    int bad = 0;
    #pragma unroll 4
    for (int i = tid; i < DD * DD; i += blockDim.x) {
        int r = i >> 6, c = i & 63;
        if (r != c && Sigma[i] != 0.0f) bad = 1;
    }
    if (bad) atomicOr(&s_offdiag, 1);
    __syncthreads();

    if (!s_offdiag) {
        if (tid < DD) {
            float v = sdiag[tid];
            g_diag[tid] = (v != 0.0f) ? 1.0f / v : 0.0f;  // pinv semantics
        }
        if (tid == 0) {
            float det = 1.0f;
            #pragma unroll
            for (int i = 0; i < DD; i++) det *= sdiag[i];  // smem, fast
            g_coef = Phi[0] / sqrtf(TWO_PI_F * det);
            g_isdiag = 1;
        }
        return;
    }

    // --- General path: Gauss-Jordan with partial pivoting on [Sigma | I] ---
    for (int i = tid; i < DD * 2 * DD; i += blockDim.x) {
        int r = i / (2 * DD), c = i % (2 * DD);
        aug[r][c] = (c < DD) ? Sigma[r * DD + c]
                             : ((c - DD == r) ? 1.0f : 0.0f);
    }
    if (tid == 0) s_det = 1.0f;
    __syncthreads();

    for (int k = 0; k < DD; k++) {
        if (tid == 0) {
            int p = k;
            float best = fabsf(aug[k][k]);
            for (int r = k + 1; r < DD; r++) {
                float v = fabsf(aug[r][k]);
                if (v > best) { best = v; p = r; }
            }
            s_piv = p;
            if (p != k) s_det = -s_det;
        }
        __syncthreads();
        int p = s_piv;
        if (p != k) {
            for (int c = tid; c < 2 * DD; c += blockDim.x) {
                float t = aug[k][c];
                aug[k][c] = aug[p][c];
                aug[p][c] = t;
            }
            __syncthreads();
        }
        float piv = aug[k][k];
        if (tid == 0) s_det *= piv;
        float inv_piv = (piv != 0.0f) ? 1.0f / piv : 0.0f;
        for (int c = tid; c < 2 * DD; c += blockDim.x) {
            aug[k][c] *= inv_piv;
        }
        if (tid < DD) colk[tid] = (tid == k) ? 0.0f : aug[tid][k];
        __syncthreads();
        for (int i = tid; i < DD * 2 * DD; i += blockDim.x) {
            int r = i / (2 * DD), c = i % (2 * DD);
            if (r != k) aug[r][c] -= colk[r] * aug[k][c];
        }
        __syncthreads();
    }

    for (int i = tid; i < DD * DD; i += blockDim.x) {
        int r = i >> 6, c = i & 63;
        g_invA[i] = aug[r][DD + c];
    }
    if (tid == 0) {
        g_coef = Phi[0] / sqrtf(TWO_PI_F * s_det);
        g_isdiag = 0;
    }
}

// ---------------------------------------------------------------------------
// Main kernel (diag fast path): 8 samples per thread, 8 independent LDG.128
// front-batched (MLP_p1 = 8). Each half-warp (16 lanes) owns an 8-sample
// group; each load j is a contiguous 256B segment per half-warp (fully
// coalesced). 8 shfl reduction trees over the 16-lane group; lane sub==0
// writes 8 consecutive NLLs via two STG.128.
// ---------------------------------------------------------------------------
__global__ void __launch_bounds__(256)
density_kernel(const float* __restrict__ x,
               const float* __restrict__ mu,
               float* __restrict__ out, int N) {
    int lane = threadIdx.x & 31;
    int warp_g = (blockIdx.x * blockDim.x + threadIdx.x) >> 5;
    int half = lane >> 4;           // 0 or 1
    int sub = lane & 15;            // 16B chunk within sample
    int base = warp_g * 16 + half * 8;  // first of this thread's 8 samples
    if (base >= N) return;

    if (g_isdiag) {
        float4 muv = reinterpret_cast<const float4*>(mu)[sub];
        float4 av  = reinterpret_cast<const float4*>(g_diag)[sub];

        // Front-batched independent loads: 8 samples, same sub-offset.
        const float4* xr = reinterpret_cast<const float4*>(x);
        float4 v[8];
        #pragma unroll
        for (int j = 0; j < 8; j++)
            v[j] = xr[(size_t)(base + j) * 16 + sub];

        float p[8];
        #pragma unroll
        for (int j = 0; j < 8; j++) {
            float d0 = v[j].x - muv.x, d1 = v[j].y - muv.y,
                  d2 = v[j].z - muv.z, d3 = v[j].w - muv.w;
            p[j] = av.x * d0 * d0 + av.y * d1 * d1 +
                   av.z * d2 * d2 + av.w * d3 * d3;
        }

        // 8 independent 16-lane reduction trees (masks < 16 keep halves
        // separate).
        #pragma unroll
        for (int m = 8; m >= 1; m >>= 1) {
            #pragma unroll
            for (int j = 0; j < 8; j++)
                p[j] += __shfl_xor_sync(0xffffffffu, p[j], m);
        }

        if (sub == 0) {
            float coef = g_coef;
            float r[8];
            #pragma unroll
            for (int j = 0; j < 8; j++)
                r[j] = -__logf(coef * __expf(-0.5f * p[j]) + EPS_F);
            float4 o0 = make_float4(r[0], r[1], r[2], r[3]);
            float4 o1 = make_float4(r[4], r[5], r[6], r[7]);
            *reinterpret_cast<float4*>(out + base) = o0;
            *reinterpret_cast<float4*>(out + base + 4) = o1;
        }
    } else {
        // General quadratic form (cold path).
        if (sub == 0) {
            for (int j = 0; j < 8; j++) {
                int s = base + j;
                if (s >= N) break;
                const float* xrow = x + (size_t)s * DD;
                float q = 0.0f;
#pragma unroll 1
                for (int e = 0; e < DD; e++) {
                    float de = xrow[e] - mu[e];
                    float t = 0.0f;
#pragma unroll 8
                    for (int d = 0; d < DD; d++)
                        t += g_invA[e * DD + d] * (xrow[d] - mu[d]);
                    q += de * t;
                }
                float dens = g_coef * __expf(-0.5f * q);
                out[s] = -__logf(dens + EPS_F);
            }
        }
    }
}

extern "C" void kernel_launch(void* const* d_in, const int* in_sizes, int n_in,
                              void* d_out, int out_size) {
    const float* samples = (const float*)d_in[0];
    const float* Phi     = (const float*)d_in[1];
    const float* mu      = (const float*)d_in[2];
    const float* Sigma   = (const float*)d_in[3];
    int N = out_size;  // one output per sample

    prep_kernel<<<1, 256>>>(Sigma, Phi);

    // 8 samples per thread, 16 lanes per sample -> N*2 threads total.
    long long total = (long long)N * 2;
    int threads = 256;
    int blocks = (int)((total + threads - 1) / threads);
    density_kernel<<<blocks, threads>>>(samples, mu, (float*)d_out, N);
}

// round 5
// speedup vs baseline: 1.0864x; 1.0864x over previous
#include <cuda_runtime.h>
#include <math.h>

#define DD 64
#define TWO_PI_F 6.283185307179586f
#define EPS_F 1e-8f

// Device-side scratch (no allocations allowed).
__device__ __align__(16) float g_diag[DD];
__device__ float g_invA[DD * DD];
__device__ float g_coef;
__device__ int g_isdiag;

// ---------------------------------------------------------------------------
// Prep kernel. Diag fast path: parallel diagonal load + smem det product.
// General path: Gauss-Jordan w/ partial pivoting, det from pivots. 1 block.
// ---------------------------------------------------------------------------
__global__ void prep_kernel(const float* __restrict__ Sigma,
                            const float* __restrict__ Phi) {
    __shared__ float aug[DD][2 * DD];
    __shared__ float colk[DD];
    __shared__ float sdiag[DD];
    __shared__ int s_offdiag;
    __shared__ float s_det;
    __shared__ int s_piv;
    int tid = threadIdx.x;

    if (tid == 0) s_offdiag = 0;
    if (tid < DD) sdiag[tid] = Sigma[tid * DD + tid];
    __syncthreads();

    int bad = 0;
    #pragma unroll 4
    for (int i = tid; i < DD * DD; i += blockDim.x) {
        int r = i >> 6, c = i & 63;
        if (r != c && Sigma[i] != 0.0f) bad = 1;
    }
    if (bad) atomicOr(&s_offdiag, 1);
    __syncthreads();

    if (!s_offdiag) {
        if (tid < DD) {
            float v = sdiag[tid];
            g_diag[tid] = (v != 0.0f) ? 1.0f / v : 0.0f;  // pinv semantics
        }
        if (tid == 0) {
            float det = 1.0f;
            #pragma unroll
            for (int i = 0; i < DD; i++) det *= sdiag[i];
            g_coef = Phi[0] / sqrtf(TWO_PI_F * det);
            g_isdiag = 1;
        }
        return;
    }

    // --- General path: Gauss-Jordan with partial pivoting on [Sigma | I] ---
    for (int i = tid; i < DD * 2 * DD; i += blockDim.x) {
        int r = i / (2 * DD), c = i % (2 * DD);
        aug[r][c] = (c < DD) ? Sigma[r * DD + c]
                             : ((c - DD == r) ? 1.0f : 0.0f);
    }
    if (tid == 0) s_det = 1.0f;
    __syncthreads();

    for (int k = 0; k < DD; k++) {
        if (tid == 0) {
            int p = k;
            float best = fabsf(aug[k][k]);
            for (int r = k + 1; r < DD; r++) {
                float v = fabsf(aug[r][k]);
                if (v > best) { best = v; p = r; }
            }
            s_piv = p;
            if (p != k) s_det = -s_det;
        }
        __syncthreads();
        int p = s_piv;
        if (p != k) {
            for (int c = tid; c < 2 * DD; c += blockDim.x) {
                float t = aug[k][c];
                aug[k][c] = aug[p][c];
                aug[p][c] = t;
            }
            __syncthreads();
        }
        float piv = aug[k][k];
        if (tid == 0) s_det *= piv;
        float inv_piv = (piv != 0.0f) ? 1.0f / piv : 0.0f;
        for (int c = tid; c < 2 * DD; c += blockDim.x) {
            aug[k][c] *= inv_piv;
        }
        if (tid < DD) colk[tid] = (tid == k) ? 0.0f : aug[tid][k];
        __syncthreads();
        for (int i = tid; i < DD * 2 * DD; i += blockDim.x) {
            int r = i / (2 * DD), c = i % (2 * DD);
            if (r != k) aug[r][c] -= colk[r] * aug[k][c];
        }
        __syncthreads();
    }

    for (int i = tid; i < DD * DD; i += blockDim.x) {
        int r = i >> 6, c = i & 63;
        g_invA[i] = aug[r][DD + c];
    }
    if (tid == 0) {
        g_coef = Phi[0] / sqrtf(TWO_PI_F * s_det);
        g_isdiag = 0;
    }
}

// ---------------------------------------------------------------------------
// Main kernel (diag fast path): 6 samples per thread (MLP_p1 = 6),
// __launch_bounds__(256, 6) to force 42-reg cap -> 6 CTAs/SM (75% occ).
// Half-warp (16 lanes) owns a 6-sample group; each front-batched __ldcs
// float4 load is a contiguous, fully-coalesced 256B segment. 6 shfl
// reduction trees; lane sub==0 writes 6 NLLs via 3x STG.64 (8B aligned:
// base is always even).
// ---------------------------------------------------------------------------
__global__ void __launch_bounds__(256, 6)
density_kernel(const float* __restrict__ x,
               const float* __restrict__ mu,
               float* __restrict__ out, int N) {
    const int G = 6;
    int lane = threadIdx.x & 31;
    int warp_g = (blockIdx.x * blockDim.x + threadIdx.x) >> 5;
    int half = lane >> 4;
    int sub = lane & 15;
    int base = warp_g * (2 * G) + half * G;  // first of this thread's G samples
    if (base >= N) return;

    if (g_isdiag) {
        float4 muv = reinterpret_cast<const float4*>(mu)[sub];
        float4 av  = reinterpret_cast<const float4*>(g_diag)[sub];
        const float4* xr = reinterpret_cast<const float4*>(x);

        float p[G];

        if (base + G <= N) {
            // Fast path: 6 front-batched streaming loads (evict-first).
            float4 v[G];
            #pragma unroll
            for (int j = 0; j < G; j++)
                v[j] = __ldcs(&xr[(size_t)(base + j) * 16 + sub]);

            #pragma unroll
            for (int j = 0; j < G; j++) {
                float d0 = v[j].x - muv.x, d1 = v[j].y - muv.y,
                      d2 = v[j].z - muv.z, d3 = v[j].w - muv.w;
                p[j] = av.x * d0 * d0 + av.y * d1 * d1 +
                       av.z * d2 * d2 + av.w * d3 * d3;
            }
        } else {
            // Tail group: guarded loads.
            #pragma unroll
            for (int j = 0; j < G; j++) {
                float4 v = make_float4(0.f, 0.f, 0.f, 0.f);
                if (base + j < N)
                    v = __ldcs(&xr[(size_t)(base + j) * 16 + sub]);
                float d0 = v.x - muv.x, d1 = v.y - muv.y,
                      d2 = v.z - muv.z, d3 = v.w - muv.w;
                p[j] = av.x * d0 * d0 + av.y * d1 * d1 +
                       av.z * d2 * d2 + av.w * d3 * d3;
            }
        }

        // 6 independent 16-lane reduction trees.
        #pragma unroll
        for (int m = 8; m >= 1; m >>= 1) {
            #pragma unroll
            for (int j = 0; j < G; j++)
                p[j] += __shfl_xor_sync(0xffffffffu, p[j], m);
        }

        if (sub == 0) {
            float coef = g_coef;
            float r[G];
            #pragma unroll
            for (int j = 0; j < G; j++)
                r[j] = -__logf(coef * __expf(-0.5f * p[j]) + EPS_F);

            if (base + G <= N) {
                // base = 6*k per half-warp pair -> always even -> 8B aligned.
                *reinterpret_cast<float2*>(out + base)     = make_float2(r[0], r[1]);
                *reinterpret_cast<float2*>(out + base + 2) = make_float2(r[2], r[3]);
                *reinterpret_cast<float2*>(out + base + 4) = make_float2(r[4], r[5]);
            } else {
                for (int j = 0; j < G; j++)
                    if (base + j < N) out[base + j] = r[j];
            }
        }
    } else {
        // General quadratic form (cold path).
        if (sub == 0) {
            for (int j = 0; j < G; j++) {
                int s = base + j;
                if (s >= N) break;
                const float* xrow = x + (size_t)s * DD;
                float q = 0.0f;
#pragma unroll 1
                for (int e = 0; e < DD; e++) {
                    float de = xrow[e] - mu[e];
                    float t = 0.0f;
#pragma unroll 8
                    for (int d = 0; d < DD; d++)
                        t += g_invA[e * DD + d] * (xrow[d] - mu[d]);
                    q += de * t;
                }
                float dens = g_coef * __expf(-0.5f * q);
                out[s] = -__logf(dens + EPS_F);
            }
        }
    }
}

extern "C" void kernel_launch(void* const* d_in, const int* in_sizes, int n_in,
                              void* d_out, int out_size) {
    const float* samples = (const float*)d_in[0];
    const float* Phi     = (const float*)d_in[1];
    const float* mu      = (const float*)d_in[2];
    const float* Sigma   = (const float*)d_in[3];
    int N = out_size;  // one output per sample

    prep_kernel<<<1, 256>>>(Sigma, Phi);

    // 6 samples per thread, 16 lanes per sample.
    long long groups = (N + 5) / 6;          // sample groups of 6
    long long total = groups * 16;           // threads
    int threads = 256;
    int blocks = (int)((total + threads - 1) / threads);
    density_kernel<<<blocks, threads>>>(samples, mu, (float*)d_out, N);
}

// round 6
// speedup vs baseline: 1.1909x; 1.0961x over previous
#include <cuda_runtime.h>
#include <math.h>

#define DD 64
#define TWO_PI_F 6.283185307179586f
#define EPS_F 1e-8f

// Device-side scratch (no allocations allowed).
__device__ __align__(16) float g_diag[DD];
__device__ float g_invA[DD * DD];
__device__ float g_coef;
__device__ int g_isdiag;

// ---------------------------------------------------------------------------
// Prep kernel. Diag fast path: parallel diagonal load + smem det product.
// General path: Gauss-Jordan w/ partial pivoting, det from pivots. 1 block.
// ---------------------------------------------------------------------------
__global__ void prep_kernel(const float* __restrict__ Sigma,
                            const float* __restrict__ Phi) {
    __shared__ float aug[DD][2 * DD];
    __shared__ float colk[DD];
    __shared__ float sdiag[DD];
    __shared__ int s_offdiag;
    __shared__ float s_det;
    __shared__ int s_piv;
    int tid = threadIdx.x;

    if (tid == 0) s_offdiag = 0;
    if (tid < DD) sdiag[tid] = Sigma[tid * DD + tid];
    __syncthreads();

    int bad = 0;
    #pragma unroll 4
    for (int i = tid; i < DD * DD; i += blockDim.x) {
        int r = i >> 6, c = i & 63;
        if (r != c && Sigma[i] != 0.0f) bad = 1;
    }
    if (bad) atomicOr(&s_offdiag, 1);
    __syncthreads();

    if (!s_offdiag) {
        if (tid < DD) {
            float v = sdiag[tid];
            g_diag[tid] = (v != 0.0f) ? 1.0f / v : 0.0f;  // pinv semantics
        }
        if (tid == 0) {
            float det = 1.0f;
            #pragma unroll
            for (int i = 0; i < DD; i++) det *= sdiag[i];
            g_coef = Phi[0] / sqrtf(TWO_PI_F * det);
            g_isdiag = 1;
        }
        return;
    }

    // --- General path: Gauss-Jordan with partial pivoting on [Sigma | I] ---
    for (int i = tid; i < DD * 2 * DD; i += blockDim.x) {
        int r = i / (2 * DD), c = i % (2 * DD);
        aug[r][c] = (c < DD) ? Sigma[r * DD + c]
                             : ((c - DD == r) ? 1.0f : 0.0f);
    }
    if (tid == 0) s_det = 1.0f;
    __syncthreads();

    for (int k = 0; k < DD; k++) {
        if (tid == 0) {
            int p = k;
            float best = fabsf(aug[k][k]);
            for (int r = k + 1; r < DD; r++) {
                float v = fabsf(aug[r][k]);
                if (v > best) { best = v; p = r; }
            }
            s_piv = p;
            if (p != k) s_det = -s_det;
        }
        __syncthreads();
        int p = s_piv;
        if (p != k) {
            for (int c = tid; c < 2 * DD; c += blockDim.x) {
                float t = aug[k][c];
                aug[k][c] = aug[p][c];
                aug[p][c] = t;
            }
            __syncthreads();
        }
        float piv = aug[k][k];
        if (tid == 0) s_det *= piv;
        float inv_piv = (piv != 0.0f) ? 1.0f / piv : 0.0f;
        for (int c = tid; c < 2 * DD; c += blockDim.x) {
            aug[k][c] *= inv_piv;
        }
        if (tid < DD) colk[tid] = (tid == k) ? 0.0f : aug[tid][k];
        __syncthreads();
        for (int i = tid; i < DD * 2 * DD; i += blockDim.x) {
            int r = i / (2 * DD), c = i % (2 * DD);
            if (r != k) aug[r][c] -= colk[r] * aug[k][c];
        }
        __syncthreads();
    }

    for (int i = tid; i < DD * DD; i += blockDim.x) {
        int r = i >> 6, c = i & 63;
        g_invA[i] = aug[r][DD + c];
    }
    if (tid == 0) {
        g_coef = Phi[0] / sqrtf(TWO_PI_F * s_det);
        g_isdiag = 0;
    }
}

// ---------------------------------------------------------------------------
// Main kernel (diag fast path): R3-proven config. 4 samples per thread,
// 4 independent front-batched __ldcs LDG.128 (MLP_p1=4), 32 regs, 8 CTAs/SM.
// Half-warp (16 lanes) owns a 4-sample group; load j is a contiguous,
// fully-coalesced 256B segment. 4 shfl reduction trees; lane sub==0 writes
// 4 consecutive NLLs via one STG.128.
// ---------------------------------------------------------------------------
__global__ void __launch_bounds__(256, 8)
density_kernel(const float* __restrict__ x,
               const float* __restrict__ mu,
               float* __restrict__ out, int N) {
    int lane = threadIdx.x & 31;
    int warp_g = (blockIdx.x * blockDim.x + threadIdx.x) >> 5;
    int half = lane >> 4;          // 0 or 1
    int sub = lane & 15;           // 16B chunk within sample
    int base = warp_g * 8 + half * 4;   // first of this thread's 4 samples
    if (base >= N) return;

    if (g_isdiag) {
        float4 muv = reinterpret_cast<const float4*>(mu)[sub];
        float4 av  = reinterpret_cast<const float4*>(g_diag)[sub];

        // Front-batched independent streaming loads (read-once data).
        const float4* xr = reinterpret_cast<const float4*>(x);
        float4 xv0 = __ldcs(&xr[(size_t)(base + 0) * 16 + sub]);
        float4 xv1 = __ldcs(&xr[(size_t)(base + 1) * 16 + sub]);
        float4 xv2 = __ldcs(&xr[(size_t)(base + 2) * 16 + sub]);
        float4 xv3 = __ldcs(&xr[(size_t)(base + 3) * 16 + sub]);

        float p0, p1, p2, p3;
        {
            float d0 = xv0.x - muv.x, d1 = xv0.y - muv.y,
                  d2 = xv0.z - muv.z, d3 = xv0.w - muv.w;
            p0 = av.x * d0 * d0 + av.y * d1 * d1 + av.z * d2 * d2 + av.w * d3 * d3;
        }
        {
            float d0 = xv1.x - muv.x, d1 = xv1.y - muv.y,
                  d2 = xv1.z - muv.z, d3 = xv1.w - muv.w;
            p1 = av.x * d0 * d0 + av.y * d1 * d1 + av.z * d2 * d2 + av.w * d3 * d3;
        }
        {
            float d0 = xv2.x - muv.x, d1 = xv2.y - muv.y,
                  d2 = xv2.z - muv.z, d3 = xv2.w - muv.w;
            p2 = av.x * d0 * d0 + av.y * d1 * d1 + av.z * d2 * d2 + av.w * d3 * d3;
        }
        {
            float d0 = xv3.x - muv.x, d1 = xv3.y - muv.y,
                  d2 = xv3.z - muv.z, d3 = xv3.w - muv.w;
            p3 = av.x * d0 * d0 + av.y * d1 * d1 + av.z * d2 * d2 + av.w * d3 * d3;
        }

        // 4 independent 16-lane reduction trees (masks < 16 keep halves
        // separate).
        #pragma unroll
        for (int m = 8; m >= 1; m >>= 1) {
            p0 += __shfl_xor_sync(0xffffffffu, p0, m);
            p1 += __shfl_xor_sync(0xffffffffu, p1, m);
            p2 += __shfl_xor_sync(0xffffffffu, p2, m);
            p3 += __shfl_xor_sync(0xffffffffu, p3, m);
        }

        if (sub == 0) {
            float coef = g_coef;
            float4 r;
            r.x = -__logf(coef * __expf(-0.5f * p0) + EPS_F);
            r.y = -__logf(coef * __expf(-0.5f * p1) + EPS_F);
            r.z = -__logf(coef * __expf(-0.5f * p2) + EPS_F);
            r.w = -__logf(coef * __expf(-0.5f * p3) + EPS_F);
            *reinterpret_cast<float4*>(out + base) = r;
        }
    } else {
        // General quadratic form (cold path).
        if (sub == 0) {
            for (int j = 0; j < 4; j++) {
                int s = base + j;
                if (s >= N) break;
                const float* xrow = x + (size_t)s * DD;
                float q = 0.0f;
#pragma unroll 1
                for (int e = 0; e < DD; e++) {
                    float de = xrow[e] - mu[e];
                    float t = 0.0f;
#pragma unroll 8
                    for (int d = 0; d < DD; d++)
                        t += g_invA[e * DD + d] * (xrow[d] - mu[d]);
                    q += de * t;
                }
                float dens = g_coef * __expf(-0.5f * q);
                out[s] = -__logf(dens + EPS_F);
            }
        }
    }
}

extern "C" void kernel_launch(void* const* d_in, const int* in_sizes, int n_in,
                              void* d_out, int out_size) {
    const float* samples = (const float*)d_in[0];
    const float* Phi     = (const float*)d_in[1];
    const float* mu      = (const float*)d_in[2];
    const float* Sigma   = (const float*)d_in[3];
    int N = out_size;  // one output per sample

    prep_kernel<<<1, 256>>>(Sigma, Phi);

    // 4 samples per thread, 16 lanes per sample -> N*4 threads total.
    long long total = (long long)N * 4;
    int threads = 256;
    int blocks = (int)((total + threads - 1) / threads);
    density_kernel<<<blocks, threads>>>(samples, mu, (float*)d_out, N);
}